// round 2
// baseline (speedup 1.0000x reference)
#include <cuda_runtime.h>
#include <cuda_bf16.h>
#include <mma.h>
#include <cstdint>

using namespace nvcuda;

// Problem constants
#define Bc   8
#define Nn   4096
#define DIM  1536
#define Hh   24
#define HD   64
#define Rr   8
#define JH   (Hh * Rr)          // 192
#define SCALE 0.125f            // 64^-0.5
#define MASKW (Nn - Rr)         // 4088

// ---------------- scratch (device globals; no allocation allowed) ----------
__device__ float g_q[Bc * Hh * Rr * HD];     // [b][h][r][d]
__device__ float g_G[Bc * JH * DIM];         // [b][j=h*R+r][c]
__device__ float g_S[(size_t)Bc * JH * Nn];  // [b][j][n]  logits -> probs (in place)
__device__ float g_Y[Bc * JH * DIM];         // [b][j][c]
__device__ float g_xcls[Bc * Rr * DIM];      // [b][r][e]

// ============================================================================
// K1a: q[b][h][r][d] = SCALE * dot(x[b,r,:], Wq[h*64+d,:])   (r < 8)
// grid 192 = (b,h), 256 threads
// ============================================================================
__global__ void k_qproj(const float* __restrict__ x, const float* __restrict__ Wq) {
    int b = blockIdx.x / Hh, h = blockIdx.x % Hh;
    __shared__ float xs[Rr * DIM];                  // 48KB: first 8 token rows
    const float* xb = x + (size_t)b * Nn * DIM;
    for (int i = threadIdx.x; i < Rr * DIM; i += 256) xs[i] = xb[i];
    __syncthreads();
    int warp = threadIdx.x >> 5, lane = threadIdx.x & 31;
    #pragma unroll 1
    for (int i = 0; i < 8; i++) {
        int d = warp * 8 + i;
        const float* wrow = Wq + (size_t)(h * HD + d) * DIM;
        float acc[8] = {0.f,0.f,0.f,0.f,0.f,0.f,0.f,0.f};
        for (int c = lane; c < DIM; c += 32) {
            float w = wrow[c];
            #pragma unroll
            for (int r = 0; r < 8; r++) acc[r] += w * xs[r * DIM + c];
        }
        #pragma unroll
        for (int r = 0; r < 8; r++)
            #pragma unroll
            for (int off = 16; off > 0; off >>= 1)
                acc[r] += __shfl_xor_sync(0xffffffffu, acc[r], off);
        if (lane < 8)
            g_q[(((size_t)b * Hh + h) * Rr + lane) * HD + d] = acc[lane] * SCALE;
    }
}

// ============================================================================
// K1b: G[b][h*R+r][c] = sum_d q[b][h][r][d] * Wk[h*64+d][c]
// grid 192 = (b,h), 256 threads
// ============================================================================
__global__ void k_gproj(const float* __restrict__ Wk) {
    int b = blockIdx.x / Hh, h = blockIdx.x % Hh;
    __shared__ float qs[Rr * HD];
    for (int i = threadIdx.x; i < Rr * HD; i += 256)
        qs[i] = g_q[((size_t)(b * Hh + h)) * Rr * HD + i];
    __syncthreads();
    float acc[6][8];
    #pragma unroll
    for (int cc = 0; cc < 6; cc++)
        #pragma unroll
        for (int r = 0; r < 8; r++) acc[cc][r] = 0.f;
    const float* wbase = Wk + (size_t)(h * HD) * DIM;
    #pragma unroll 4
    for (int d = 0; d < HD; d++) {
        #pragma unroll
        for (int cc = 0; cc < 6; cc++) {
            int c = cc * 256 + threadIdx.x;
            float w = wbase[(size_t)d * DIM + c];
            #pragma unroll
            for (int r = 0; r < 8; r++) acc[cc][r] += qs[r * HD + d] * w;
        }
    }
    #pragma unroll
    for (int cc = 0; cc < 6; cc++)
        #pragma unroll
        for (int r = 0; r < 8; r++)
            g_G[((size_t)b * JH + h * Rr + r) * DIM + cc * 256 + threadIdx.x] = acc[cc][r];
}

// ============================================================================
// K2: S[b][j][n] = sum_c G[b][j][c] * x[b][n][c]   (tf32 wmma)
// M=192(j), N=4096(n), K=1536 per batch. CTA tile 64x64, k-chunk 32.
// grid (64 n-tiles, 3 j-tiles, 8 b), 256 threads (8 warps, 4x2)
// ============================================================================
#define LDA 40
__global__ void k_gemmS(const float* __restrict__ x) {
    __shared__ float As[64 * LDA];   // As[m][k]  (G rows)
    __shared__ float Bs[64 * LDA];   // Bs[n][k]  (x rows) -> col-major (k,n)
    int b = blockIdx.z;
    int j0 = blockIdx.y * 64, n0 = blockIdx.x * 64;
    const float* Gb = g_G + (size_t)b * JH * DIM;
    const float* xb = x   + (size_t)b * Nn * DIM;
    int tid = threadIdx.x;
    int warp = tid >> 5, wm = warp >> 1, wn = warp & 1;

    wmma::fragment<wmma::matrix_a, 16, 16, 8, wmma::precision::tf32, wmma::row_major> af;
    wmma::fragment<wmma::matrix_b, 16, 16, 8, wmma::precision::tf32, wmma::col_major> bf0, bf1;
    wmma::fragment<wmma::accumulator, 16, 16, 8, float> c0, c1;
    wmma::fill_fragment(c0, 0.f);
    wmma::fill_fragment(c1, 0.f);

    for (int k0 = 0; k0 < DIM; k0 += 32) {
        __syncthreads();
        #pragma unroll
        for (int i = tid; i < 512; i += 256) {
            int row = i >> 3, kk = (i & 7) << 2;
            *(float4*)&As[row * LDA + kk] = *(const float4*)&Gb[(size_t)(j0 + row) * DIM + k0 + kk];
            *(float4*)&Bs[row * LDA + kk] = *(const float4*)&xb[(size_t)(n0 + row) * DIM + k0 + kk];
        }
        __syncthreads();
        #pragma unroll
        for (int kk = 0; kk < 32; kk += 8) {
            wmma::load_matrix_sync(af,  &As[(wm * 16) * LDA + kk], LDA);
            wmma::load_matrix_sync(bf0, &Bs[(wn * 32) * LDA + kk], LDA);
            wmma::load_matrix_sync(bf1, &Bs[(wn * 32 + 16) * LDA + kk], LDA);
            #pragma unroll
            for (int t = 0; t < af.num_elements; t++)  af.x[t]  = wmma::__float_to_tf32(af.x[t]);
            #pragma unroll
            for (int t = 0; t < bf0.num_elements; t++) bf0.x[t] = wmma::__float_to_tf32(bf0.x[t]);
            #pragma unroll
            for (int t = 0; t < bf1.num_elements; t++) bf1.x[t] = wmma::__float_to_tf32(bf1.x[t]);
            wmma::mma_sync(c0, af, bf0, c0);
            wmma::mma_sync(c1, af, bf1, c1);
        }
    }
    float* Sb = g_S + (size_t)b * JH * Nn;
    wmma::store_matrix_sync(&Sb[(size_t)(j0 + wm * 16) * Nn + n0 + wn * 32],      c0, Nn, wmma::mem_row_major);
    wmma::store_matrix_sync(&Sb[(size_t)(j0 + wm * 16) * Nn + n0 + wn * 32 + 16], c1, Nn, wmma::mem_row_major);
}

// ============================================================================
// K3: masked softmax over n for each row S[b][j][:]   (in place -> probs)
// valid(n): n<8 ? (n==r) : mask[b][r][n-8]!=0    (r = j % 8)
// mask is int32 on the wire (harness materializes jax bool_ as int32)
// grid 1536, 256 threads
// ============================================================================
__global__ void k_softmax(const int* __restrict__ mask) {
    int bj = blockIdx.x;
    int b = bj / JH, j = bj % JH, r = j % Rr;
    float* row = g_S + (size_t)bj * Nn;
    const int* mrow = mask + ((size_t)b * Rr + r) * MASKW;
    int tid = threadIdx.x, warp = tid >> 5, lane = tid & 31;
    __shared__ float red[8];

    float mx = -3.0e38f;
    for (int n = tid; n < Nn; n += 256) {
        bool valid = (n < Rr) ? (n == r) : (mrow[n - Rr] != 0);
        if (valid) mx = fmaxf(mx, row[n]);
    }
    #pragma unroll
    for (int off = 16; off > 0; off >>= 1) mx = fmaxf(mx, __shfl_xor_sync(0xffffffffu, mx, off));
    if (lane == 0) red[warp] = mx;
    __syncthreads();
    if (warp == 0) {
        float v = (lane < 8) ? red[lane] : -3.0e38f;
        #pragma unroll
        for (int off = 4; off > 0; off >>= 1) v = fmaxf(v, __shfl_xor_sync(0xffffffffu, v, off));
        if (lane == 0) red[0] = v;
    }
    __syncthreads();
    mx = red[0];
    __syncthreads();

    float sum = 0.f;
    for (int n = tid; n < Nn; n += 256) {
        bool valid = (n < Rr) ? (n == r) : (mrow[n - Rr] != 0);
        float e = valid ? __expf(row[n] - mx) : 0.f;
        row[n] = e;
        sum += e;
    }
    #pragma unroll
    for (int off = 16; off > 0; off >>= 1) sum += __shfl_xor_sync(0xffffffffu, sum, off);
    if (lane == 0) red[warp] = sum;
    __syncthreads();
    if (warp == 0) {
        float v = (lane < 8) ? red[lane] : 0.f;
        #pragma unroll
        for (int off = 4; off > 0; off >>= 1) v += __shfl_xor_sync(0xffffffffu, v, off);
        if (lane == 0) red[0] = v;
    }
    __syncthreads();
    float inv = 1.f / red[0];
    for (int n = tid; n < Nn; n += 256) row[n] *= inv;
}

// ============================================================================
// K4: Y[b][j][c] = sum_n P[b][j][n] * x[b][n][c]   (tf32 wmma)
// M=192(j), N=1536(c), K=4096(n). CTA 64x64, k-chunk 32.
// grid (24 c-tiles, 3 j-tiles, 8 b), 256 threads
// ============================================================================
#define LDB4 72
__global__ void k_gemmY(const float* __restrict__ x) {
    __shared__ float As[64 * LDA];    // As[m=j][k=n]
    __shared__ float Bs[32 * LDB4];   // Bs[k=n][col=c]  row-major
    int b = blockIdx.z;
    int j0 = blockIdx.y * 64, c0 = blockIdx.x * 64;
    const float* Pb = g_S + (size_t)b * JH * Nn;
    const float* xb = x   + (size_t)b * Nn * DIM;
    int tid = threadIdx.x;
    int warp = tid >> 5, wm = warp >> 1, wn = warp & 1;

    wmma::fragment<wmma::matrix_a, 16, 16, 8, wmma::precision::tf32, wmma::row_major> af;
    wmma::fragment<wmma::matrix_b, 16, 16, 8, wmma::precision::tf32, wmma::row_major> bf0, bf1;
    wmma::fragment<wmma::accumulator, 16, 16, 8, float> c0f, c1f;
    wmma::fill_fragment(c0f, 0.f);
    wmma::fill_fragment(c1f, 0.f);

    for (int k0 = 0; k0 < Nn; k0 += 32) {
        __syncthreads();
        #pragma unroll
        for (int i = tid; i < 512; i += 256) {
            int rowA = i >> 3, kkA = (i & 7) << 2;
            *(float4*)&As[rowA * LDA + kkA] = *(const float4*)&Pb[(size_t)(j0 + rowA) * Nn + k0 + kkA];
            int rowB = i >> 4, ccB = (i & 15) << 2;
            *(float4*)&Bs[rowB * LDB4 + ccB] = *(const float4*)&xb[(size_t)(k0 + rowB) * DIM + c0 + ccB];
        }
        __syncthreads();
        #pragma unroll
        for (int kk = 0; kk < 32; kk += 8) {
            wmma::load_matrix_sync(af,  &As[(wm * 16) * LDA + kk], LDA);
            wmma::load_matrix_sync(bf0, &Bs[kk * LDB4 + wn * 32], LDB4);
            wmma::load_matrix_sync(bf1, &Bs[kk * LDB4 + wn * 32 + 16], LDB4);
            #pragma unroll
            for (int t = 0; t < af.num_elements; t++)  af.x[t]  = wmma::__float_to_tf32(af.x[t]);
            #pragma unroll
            for (int t = 0; t < bf0.num_elements; t++) bf0.x[t] = wmma::__float_to_tf32(bf0.x[t]);
            #pragma unroll
            for (int t = 0; t < bf1.num_elements; t++) bf1.x[t] = wmma::__float_to_tf32(bf1.x[t]);
            wmma::mma_sync(c0f, af, bf0, c0f);
            wmma::mma_sync(c1f, af, bf1, c1f);
        }
    }
    float* Yb = g_Y + (size_t)b * JH * DIM;
    wmma::store_matrix_sync(&Yb[(size_t)(j0 + wm * 16) * DIM + c0 + wn * 32],      c0f, DIM, wmma::mem_row_major);
    wmma::store_matrix_sync(&Yb[(size_t)(j0 + wm * 16) * DIM + c0 + wn * 32 + 16], c1f, DIM, wmma::mem_row_major);
}

// ============================================================================
// K5a: x_cls[b][r][e] = sum_c Y[b][(e/64)*8 + r][c] * Wv[e][c]
// grid 192 = (b,h), 256 threads
// ============================================================================
__global__ void k_xcls(const float* __restrict__ Wv) {
    int b = blockIdx.x / Hh, h = blockIdx.x % Hh;
    __shared__ float Ys[Rr * DIM];                 // 48KB : Y rows j = h*8 .. h*8+7
    for (int i = threadIdx.x; i < Rr * DIM; i += 256)
        Ys[i] = g_Y[((size_t)b * JH + h * Rr) * DIM + i];
    __syncthreads();
    int warp = threadIdx.x >> 5, lane = threadIdx.x & 31;
    #pragma unroll 1
    for (int i = 0; i < 8; i++) {
        int e = h * HD + warp * 8 + i;
        const float* wrow = Wv + (size_t)e * DIM;
        float acc[8] = {0.f,0.f,0.f,0.f,0.f,0.f,0.f,0.f};
        for (int c = lane; c < DIM; c += 32) {
            float w = wrow[c];
            #pragma unroll
            for (int r = 0; r < 8; r++) acc[r] += w * Ys[r * DIM + c];
        }
        #pragma unroll
        for (int r = 0; r < 8; r++)
            #pragma unroll
            for (int off = 16; off > 0; off >>= 1)
                acc[r] += __shfl_xor_sync(0xffffffffu, acc[r], off);
        if (lane < 8)
            g_xcls[((size_t)b * Rr + lane) * DIM + e] = acc[lane];
    }
}

// ============================================================================
// K5b: out[b][r][o] = dot(x_cls[b][r][:], Wp[o][:]) + bp[o]
// grid 192 = (b, 24 o-blocks of 64), 256 threads
// ============================================================================
__global__ void k_out(const float* __restrict__ Wp, const float* __restrict__ bp,
                      float* __restrict__ out) {
    int b = blockIdx.x / Hh, oblk = blockIdx.x % Hh;
    __shared__ float xcs[Rr * DIM];
    for (int i = threadIdx.x; i < Rr * DIM; i += 256)
        xcs[i] = g_xcls[(size_t)b * Rr * DIM + i];
    __syncthreads();
    int warp = threadIdx.x >> 5, lane = threadIdx.x & 31;
    #pragma unroll 1
    for (int i = 0; i < 8; i++) {
        int o = oblk * HD + warp * 8 + i;
        const float* wrow = Wp + (size_t)o * DIM;
        float acc[8] = {0.f,0.f,0.f,0.f,0.f,0.f,0.f,0.f};
        for (int c = lane; c < DIM; c += 32) {
            float w = wrow[c];
            #pragma unroll
            for (int r = 0; r < 8; r++) acc[r] += w * xcs[r * DIM + c];
        }
        #pragma unroll
        for (int r = 0; r < 8; r++)
            #pragma unroll
            for (int off = 16; off > 0; off >>= 1)
                acc[r] += __shfl_xor_sync(0xffffffffu, acc[r], off);
        if (lane < 8)
            out[((size_t)b * Rr + lane) * DIM + o] = acc[lane] + bp[o];
    }
}

// ============================================================================
extern "C" void kernel_launch(void* const* d_in, const int* in_sizes, int n_in,
                              void* d_out, int out_size) {
    const float* x    = (const float*)d_in[0];
    const int*   mask = (const int*)d_in[1];     // jax bool_ -> int32 on the wire
    const float* Wq   = (const float*)d_in[2];
    const float* Wk   = (const float*)d_in[3];
    const float* Wv   = (const float*)d_in[4];
    const float* Wp   = (const float*)d_in[5];
    const float* bp   = (const float*)d_in[6];
    float*       out  = (float*)d_out;

    k_qproj  <<<Bc * Hh, 256>>>(x, Wq);
    k_gproj  <<<Bc * Hh, 256>>>(Wk);
    k_gemmS  <<<dim3(Nn / 64, JH / 64, Bc), 256>>>(x);
    k_softmax<<<Bc * JH, 256>>>(mask);
    k_gemmY  <<<dim3(DIM / 64, JH / 64, Bc), 256>>>(x);
    k_xcls   <<<Bc * Hh, 256>>>(Wv);
    k_out    <<<Bc * Hh, 256>>>(Wp, bp, out);
}

// round 3
// speedup vs baseline: 1.3887x; 1.3887x over previous
#include <cuda_runtime.h>
#include <cuda_bf16.h>
#include <mma.h>
#include <cstdint>

using namespace nvcuda;

// Problem constants
#define Bc   8
#define Nn   4096
#define DIM  1536
#define Hh   24
#define HD   64
#define Rr   8
#define JH   (Hh * Rr)          // 192
#define SCALE 0.125f            // 64^-0.5
#define MASKW (Nn - Rr)         // 4088

// ---------------- scratch (device globals; no allocation allowed) ----------
__device__ float g_G[Bc * JH * DIM];         // [b][j=h*R+r][c]
__device__ float g_S[(size_t)Bc * JH * Nn];  // [b][j][n]  logits -> probs (in place)
__device__ float g_Y[Bc * JH * DIM];         // [b][j][c]
__device__ float g_xcls[Bc * Rr * DIM];      // [b][r][e]

// ---------------- cp.async helpers ----------------
__device__ __forceinline__ void cp16(void* s, const void* g) {
    uint32_t sa = (uint32_t)__cvta_generic_to_shared(s);
    asm volatile("cp.async.ca.shared.global [%0], [%1], 16;" :: "r"(sa), "l"(g));
}
__device__ __forceinline__ void cp_commit() { asm volatile("cp.async.commit_group;"); }
template<int N> __device__ __forceinline__ void cp_wait() {
    asm volatile("cp.async.wait_group %0;" :: "n"(N));
}

// ============================================================================
// K1 (fused): q = SCALE * x[:8] @ Wq_h^T  ->  G[j] = q @ Wk_h   per (b,h)
// grid 192 = (b,h), 256 threads
// ============================================================================
__global__ void __launch_bounds__(256) k_qg(const float* __restrict__ x,
                                            const float* __restrict__ Wq,
                                            const float* __restrict__ Wk) {
    int b = blockIdx.x / Hh, h = blockIdx.x % Hh;
    __shared__ float xs[Rr * DIM];                  // 48KB: first 8 token rows (later reused for q)
    const float* xb = x + (size_t)b * Nn * DIM;
    for (int i = threadIdx.x; i < Rr * DIM; i += 256) xs[i] = xb[i];
    __syncthreads();
    int warp = threadIdx.x >> 5, lane = threadIdx.x & 31;

    // phase 1: q[r][d] for d = warp*8 + i
    float qv[8];
    #pragma unroll 1
    for (int i = 0; i < 8; i++) {
        int d = warp * 8 + i;
        const float* wrow = Wq + (size_t)(h * HD + d) * DIM;
        float acc[8] = {0.f,0.f,0.f,0.f,0.f,0.f,0.f,0.f};
        for (int c = lane; c < DIM; c += 32) {
            float w = wrow[c];
            #pragma unroll
            for (int r = 0; r < 8; r++) acc[r] += w * xs[r * DIM + c];
        }
        #pragma unroll
        for (int r = 0; r < 8; r++)
            #pragma unroll
            for (int off = 16; off > 0; off >>= 1)
                acc[r] += __shfl_xor_sync(0xffffffffu, acc[r], off);
        qv[i] = (lane < 8) ? acc[lane] * SCALE : 0.f;
    }
    __syncthreads();                                 // everyone done reading xs
    if (lane < 8) {
        #pragma unroll
        for (int i = 0; i < 8; i++)
            xs[lane * HD + warp * 8 + i] = qv[i];    // qs[r][d] in first 2KB of xs
    }
    __syncthreads();

    // phase 2: G[h*8+r][c] = sum_d qs[r][d] * Wk[h*64+d][c]
    float acc[6][8];
    #pragma unroll
    for (int cc = 0; cc < 6; cc++)
        #pragma unroll
        for (int r = 0; r < 8; r++) acc[cc][r] = 0.f;
    const float* wbase = Wk + (size_t)(h * HD) * DIM;
    #pragma unroll 4
    for (int d = 0; d < HD; d++) {
        #pragma unroll
        for (int cc = 0; cc < 6; cc++) {
            int c = cc * 256 + threadIdx.x;
            float w = wbase[(size_t)d * DIM + c];
            #pragma unroll
            for (int r = 0; r < 8; r++) acc[cc][r] += xs[r * HD + d] * w;
        }
    }
    #pragma unroll
    for (int cc = 0; cc < 6; cc++)
        #pragma unroll
        for (int r = 0; r < 8; r++)
            g_G[((size_t)b * JH + h * Rr + r) * DIM + cc * 256 + threadIdx.x] = acc[cc][r];
}

// ============================================================================
// K2: S[b][j][n] = sum_c G[b][j][c] * x[b][n][c]   (tf32 wmma, cp.async pipe)
// CTA tile 64(j) x 128(n), k-chunk 16, double buffered. 8 warps 2x4, warp 32x32.
// grid (Nn/128=32, JH/64=3, Bc), 256 threads
// ============================================================================
#define LDK 20
#define NCS (DIM / 16)    // 96
__global__ void __launch_bounds__(256) k_gemmS(const float* __restrict__ x) {
    __shared__ float As[2][64 * LDK];    // As[m=j][k]
    __shared__ float Bs[2][128 * LDK];   // Bs[n][k]  (col-major view for wmma b)
    int b = blockIdx.z;
    int j0 = blockIdx.y * 64, n0 = blockIdx.x * 128;
    const float* Gb = g_G + ((size_t)b * JH + j0) * DIM;
    const float* xb = x + ((size_t)b * Nn + n0) * DIM;
    int tid = threadIdx.x;
    int warp = tid >> 5, wm = warp >> 2, wn = warp & 3;

    int arow = tid >> 2, akseg = (tid & 3) << 2;     // 64 rows x 4 segs

    wmma::fragment<wmma::matrix_a, 16, 16, 8, wmma::precision::tf32, wmma::row_major> a0, a1;
    wmma::fragment<wmma::matrix_b, 16, 16, 8, wmma::precision::tf32, wmma::col_major> b0, b1;
    wmma::fragment<wmma::accumulator, 16, 16, 8, float> c[2][2];
    #pragma unroll
    for (int mi = 0; mi < 2; mi++)
        #pragma unroll
        for (int ni = 0; ni < 2; ni++) wmma::fill_fragment(c[mi][ni], 0.f);

    // prefetch chunk 0
    {
        cp16(&As[0][arow * LDK + akseg], &Gb[(size_t)arow * DIM + akseg]);
        cp16(&Bs[0][arow * LDK + akseg], &xb[(size_t)arow * DIM + akseg]);
        cp16(&Bs[0][(arow + 64) * LDK + akseg], &xb[(size_t)(arow + 64) * DIM + akseg]);
        cp_commit();
    }
    for (int kc = 0; kc < NCS; kc++) {
        if (kc + 1 < NCS) {
            int k0 = (kc + 1) << 4, nb = (kc + 1) & 1;
            cp16(&As[nb][arow * LDK + akseg], &Gb[(size_t)arow * DIM + k0 + akseg]);
            cp16(&Bs[nb][arow * LDK + akseg], &xb[(size_t)arow * DIM + k0 + akseg]);
            cp16(&Bs[nb][(arow + 64) * LDK + akseg], &xb[(size_t)(arow + 64) * DIM + k0 + akseg]);
            cp_commit();
            cp_wait<1>();
        } else {
            cp_wait<0>();
        }
        __syncthreads();
        int buf = kc & 1;
        #pragma unroll
        for (int kk = 0; kk < 16; kk += 8) {
            wmma::load_matrix_sync(a0, &As[buf][(wm * 32) * LDK + kk], LDK);
            wmma::load_matrix_sync(a1, &As[buf][(wm * 32 + 16) * LDK + kk], LDK);
            wmma::load_matrix_sync(b0, &Bs[buf][(wn * 32) * LDK + kk], LDK);
            wmma::load_matrix_sync(b1, &Bs[buf][(wn * 32 + 16) * LDK + kk], LDK);
            #pragma unroll
            for (int t = 0; t < a0.num_elements; t++) { a0.x[t] = wmma::__float_to_tf32(a0.x[t]); a1.x[t] = wmma::__float_to_tf32(a1.x[t]); }
            #pragma unroll
            for (int t = 0; t < b0.num_elements; t++) { b0.x[t] = wmma::__float_to_tf32(b0.x[t]); b1.x[t] = wmma::__float_to_tf32(b1.x[t]); }
            wmma::mma_sync(c[0][0], a0, b0, c[0][0]);
            wmma::mma_sync(c[0][1], a0, b1, c[0][1]);
            wmma::mma_sync(c[1][0], a1, b0, c[1][0]);
            wmma::mma_sync(c[1][1], a1, b1, c[1][1]);
        }
        __syncthreads();
    }
    float* Sb = g_S + (size_t)b * JH * Nn;
    #pragma unroll
    for (int mi = 0; mi < 2; mi++)
        #pragma unroll
        for (int ni = 0; ni < 2; ni++)
            wmma::store_matrix_sync(&Sb[(size_t)(j0 + wm * 32 + mi * 16) * Nn + n0 + wn * 32 + ni * 16],
                                    c[mi][ni], Nn, wmma::mem_row_major);
}

// ============================================================================
// K3: masked softmax, single pass (row in registers). grid 1536, 256 threads
// ============================================================================
__global__ void __launch_bounds__(256) k_softmax(const int* __restrict__ mask) {
    int bj = blockIdx.x;
    int b = bj / JH, j = bj % JH, r = j % Rr;
    float* row = g_S + (size_t)bj * Nn;
    const int* mrow = mask + ((size_t)b * Rr + r) * MASKW;
    int tid = threadIdx.x, warp = tid >> 5, lane = tid & 31;
    __shared__ float red[8];

    float v[16];
    float mx = -3.0e38f;
    #pragma unroll
    for (int i = 0; i < 16; i++) {
        int n = tid + (i << 8);
        bool valid = (n < Rr) ? (n == r) : (mrow[n - Rr] != 0);
        v[i] = valid ? row[n] : -3.0e38f;
        mx = fmaxf(mx, v[i]);
    }
    #pragma unroll
    for (int off = 16; off > 0; off >>= 1) mx = fmaxf(mx, __shfl_xor_sync(0xffffffffu, mx, off));
    if (lane == 0) red[warp] = mx;
    __syncthreads();
    if (warp == 0) {
        float t = (lane < 8) ? red[lane] : -3.0e38f;
        #pragma unroll
        for (int off = 4; off > 0; off >>= 1) t = fmaxf(t, __shfl_xor_sync(0xffffffffu, t, off));
        if (lane == 0) red[0] = t;
    }
    __syncthreads();
    mx = red[0];
    __syncthreads();

    float sum = 0.f;
    #pragma unroll
    for (int i = 0; i < 16; i++) {
        v[i] = __expf(v[i] - mx);        // invalid: exp(-3e38 - mx) -> 0
        sum += v[i];
    }
    #pragma unroll
    for (int off = 16; off > 0; off >>= 1) sum += __shfl_xor_sync(0xffffffffu, sum, off);
    if (lane == 0) red[warp] = sum;
    __syncthreads();
    if (warp == 0) {
        float t = (lane < 8) ? red[lane] : 0.f;
        #pragma unroll
        for (int off = 4; off > 0; off >>= 1) t += __shfl_xor_sync(0xffffffffu, t, off);
        if (lane == 0) red[0] = t;
    }
    __syncthreads();
    float inv = 1.f / red[0];
    #pragma unroll
    for (int i = 0; i < 16; i++) row[tid + (i << 8)] = v[i] * inv;
}

// ============================================================================
// K4: Y[b][j][c] = sum_n P[b][j][n] * x[b][n][c]  (tf32 wmma, cp.async pipe)
// CTA tile 64(j) x 128(c), k-chunk 16, double buffered. 8 warps 2x4, warp 32x32.
// grid (DIM/128=12, 3, Bc), 256 threads
// ============================================================================
#define LDC 132
#define NCY (Nn / 16)    // 256
__global__ void __launch_bounds__(256) k_gemmY(const float* __restrict__ x) {
    __shared__ float As[2][64 * LDK];    // As[m=j][k=n]
    __shared__ float Bs[2][16 * LDC];    // Bs[k=n][c]  row-major
    int b = blockIdx.z;
    int j0 = blockIdx.y * 64, c0 = blockIdx.x * 128;
    const float* Pb = g_S + ((size_t)b * JH + j0) * Nn;
    const float* xb = x + (size_t)b * Nn * DIM;
    int tid = threadIdx.x;
    int warp = tid >> 5, wm = warp >> 2, wn = warp & 3;

    int arow = tid >> 2, akseg = (tid & 3) << 2;       // A: 64 rows x 4 segs
    int brow = tid >> 5, bcseg = (tid & 31) << 2;      // B: 16 rows x 32 segs (2 per thread)

    wmma::fragment<wmma::matrix_a, 16, 16, 8, wmma::precision::tf32, wmma::row_major> a0, a1;
    wmma::fragment<wmma::matrix_b, 16, 16, 8, wmma::precision::tf32, wmma::row_major> b0, b1;
    wmma::fragment<wmma::accumulator, 16, 16, 8, float> c[2][2];
    #pragma unroll
    for (int mi = 0; mi < 2; mi++)
        #pragma unroll
        for (int ni = 0; ni < 2; ni++) wmma::fill_fragment(c[mi][ni], 0.f);

    {
        cp16(&As[0][arow * LDK + akseg], &Pb[(size_t)arow * Nn + akseg]);
        cp16(&Bs[0][brow * LDC + bcseg], &xb[(size_t)brow * DIM + c0 + bcseg]);
        cp16(&Bs[0][(brow + 8) * LDC + bcseg], &xb[(size_t)(brow + 8) * DIM + c0 + bcseg]);
        cp_commit();
    }
    for (int kc = 0; kc < NCY; kc++) {
        if (kc + 1 < NCY) {
            int k0 = (kc + 1) << 4, nb = (kc + 1) & 1;
            cp16(&As[nb][arow * LDK + akseg], &Pb[(size_t)arow * Nn + k0 + akseg]);
            cp16(&Bs[nb][brow * LDC + bcseg], &xb[(size_t)(k0 + brow) * DIM + c0 + bcseg]);
            cp16(&Bs[nb][(brow + 8) * LDC + bcseg], &xb[(size_t)(k0 + brow + 8) * DIM + c0 + bcseg]);
            cp_commit();
            cp_wait<1>();
        } else {
            cp_wait<0>();
        }
        __syncthreads();
        int buf = kc & 1;
        #pragma unroll
        for (int kk = 0; kk < 16; kk += 8) {
            wmma::load_matrix_sync(a0, &As[buf][(wm * 32) * LDK + kk], LDK);
            wmma::load_matrix_sync(a1, &As[buf][(wm * 32 + 16) * LDK + kk], LDK);
            wmma::load_matrix_sync(b0, &Bs[buf][kk * LDC + wn * 32], LDC);
            wmma::load_matrix_sync(b1, &Bs[buf][kk * LDC + wn * 32 + 16], LDC);
            #pragma unroll
            for (int t = 0; t < a0.num_elements; t++) { a0.x[t] = wmma::__float_to_tf32(a0.x[t]); a1.x[t] = wmma::__float_to_tf32(a1.x[t]); }
            #pragma unroll
            for (int t = 0; t < b0.num_elements; t++) { b0.x[t] = wmma::__float_to_tf32(b0.x[t]); b1.x[t] = wmma::__float_to_tf32(b1.x[t]); }
            wmma::mma_sync(c[0][0], a0, b0, c[0][0]);
            wmma::mma_sync(c[0][1], a0, b1, c[0][1]);
            wmma::mma_sync(c[1][0], a1, b0, c[1][0]);
            wmma::mma_sync(c[1][1], a1, b1, c[1][1]);
        }
        __syncthreads();
    }
    float* Yb = g_Y + (size_t)b * JH * DIM;
    #pragma unroll
    for (int mi = 0; mi < 2; mi++)
        #pragma unroll
        for (int ni = 0; ni < 2; ni++)
            wmma::store_matrix_sync(&Yb[(size_t)(j0 + wm * 32 + mi * 16) * DIM + c0 + wn * 32 + ni * 16],
                                    c[mi][ni], DIM, wmma::mem_row_major);
}

// ============================================================================
// K5a: x_cls[b][r][e] = sum_c Y[b][(e/64)*8 + r][c] * Wv[e][c]
// grid 192 = (b,h), 256 threads
// ============================================================================
__global__ void __launch_bounds__(256) k_xcls(const float* __restrict__ Wv) {
    int b = blockIdx.x / Hh, h = blockIdx.x % Hh;
    __shared__ float Ys[Rr * DIM];
    for (int i = threadIdx.x; i < Rr * DIM; i += 256)
        Ys[i] = g_Y[((size_t)b * JH + h * Rr) * DIM + i];
    __syncthreads();
    int warp = threadIdx.x >> 5, lane = threadIdx.x & 31;
    #pragma unroll 1
    for (int i = 0; i < 8; i++) {
        int e = h * HD + warp * 8 + i;
        const float* wrow = Wv + (size_t)e * DIM;
        float acc[8] = {0.f,0.f,0.f,0.f,0.f,0.f,0.f,0.f};
        for (int c = lane; c < DIM; c += 32) {
            float w = wrow[c];
            #pragma unroll
            for (int r = 0; r < 8; r++) acc[r] += w * Ys[r * DIM + c];
        }
        #pragma unroll
        for (int r = 0; r < 8; r++)
            #pragma unroll
            for (int off = 16; off > 0; off >>= 1)
                acc[r] += __shfl_xor_sync(0xffffffffu, acc[r], off);
        if (lane < 8)
            g_xcls[((size_t)b * Rr + lane) * DIM + e] = acc[lane];
    }
}

// ============================================================================
// K5b: out[b][r][o] = dot(x_cls[b][r][:], Wp[o][:]) + bp[o]
// grid 192 = (b, 24 o-blocks of 64), 256 threads
// ============================================================================
__global__ void __launch_bounds__(256) k_out(const float* __restrict__ Wp,
                                             const float* __restrict__ bp,
                                             float* __restrict__ out) {
    int b = blockIdx.x / Hh, oblk = blockIdx.x % Hh;
    __shared__ float xcs[Rr * DIM];
    for (int i = threadIdx.x; i < Rr * DIM; i += 256)
        xcs[i] = g_xcls[(size_t)b * Rr * DIM + i];
    __syncthreads();
    int warp = threadIdx.x >> 5, lane = threadIdx.x & 31;
    #pragma unroll 1
    for (int i = 0; i < 8; i++) {
        int o = oblk * HD + warp * 8 + i;
        const float* wrow = Wp + (size_t)o * DIM;
        float acc[8] = {0.f,0.f,0.f,0.f,0.f,0.f,0.f,0.f};
        for (int c = lane; c < DIM; c += 32) {
            float w = wrow[c];
            #pragma unroll
            for (int r = 0; r < 8; r++) acc[r] += w * xcs[r * DIM + c];
        }
        #pragma unroll
        for (int r = 0; r < 8; r++)
            #pragma unroll
            for (int off = 16; off > 0; off >>= 1)
                acc[r] += __shfl_xor_sync(0xffffffffu, acc[r], off);
        if (lane < 8)
            out[((size_t)b * Rr + lane) * DIM + o] = acc[lane] + bp[o];
    }
}

// ============================================================================
extern "C" void kernel_launch(void* const* d_in, const int* in_sizes, int n_in,
                              void* d_out, int out_size) {
    const float* x    = (const float*)d_in[0];
    const int*   mask = (const int*)d_in[1];     // jax bool_ -> int32 on the wire
    const float* Wq   = (const float*)d_in[2];
    const float* Wk   = (const float*)d_in[3];
    const float* Wv   = (const float*)d_in[4];
    const float* Wp   = (const float*)d_in[5];
    const float* bp   = (const float*)d_in[6];
    float*       out  = (float*)d_out;

    k_qg     <<<Bc * Hh, 256>>>(x, Wq, Wk);
    k_gemmS  <<<dim3(Nn / 128, JH / 64, Bc), 256>>>(x);
    k_softmax<<<Bc * JH, 256>>>(mask);
    k_gemmY  <<<dim3(DIM / 128, JH / 64, Bc), 256>>>(x);
    k_xcls   <<<Bc * Hh, 256>>>(Wv);
    k_out    <<<Bc * Hh, 256>>>(Wp, bp, out);
}

// round 4
// speedup vs baseline: 1.4283x; 1.0285x over previous
#include <cuda_runtime.h>
#include <cuda_bf16.h>
#include <mma.h>
#include <cstdint>

using namespace nvcuda;

// Problem constants
#define Bc   8
#define Nn   4096
#define DIM  1536
#define Hh   24
#define HD   64
#define Rr   8
#define JH   (Hh * Rr)          // 192
#define SCALE 0.125f            // 64^-0.5
#define MASKW (Nn - Rr)         // 4088

#define KSPS 2                  // split-K for S gemm (K=1536 -> 768 each)
#define KSPY 4                  // split-K for Y gemm (K=4096 -> 1024 each)

// ---------------- scratch (device globals; no allocation allowed) ----------
__device__ float g_G[Bc * JH * DIM];                    // [b][j][c]
__device__ float g_Sp[KSPS][(size_t)Bc * JH * Nn];      // partial logits
__device__ float g_S[(size_t)Bc * JH * Nn];             // probs
__device__ float g_Yp[KSPY][Bc * JH * DIM];             // partial Y
__device__ float g_xcls[Bc * Rr * DIM];                 // [b][r][e]

// ---------------- cp.async helpers ----------------
__device__ __forceinline__ void cp16(void* s, const void* g) {
    uint32_t sa = (uint32_t)__cvta_generic_to_shared(s);
    asm volatile("cp.async.ca.shared.global [%0], [%1], 16;" :: "r"(sa), "l"(g));
}
__device__ __forceinline__ void cp_commit() { asm volatile("cp.async.commit_group;"); }
template<int N> __device__ __forceinline__ void cp_wait() {
    asm volatile("cp.async.wait_group %0;" :: "n"(N));
}

// ============================================================================
// K1 (fused): q = SCALE * x[:8] @ Wq_h^T  ->  G[j] = q @ Wk_h   per (b,h)
// grid 192 = (b,h), 256 threads
// ============================================================================
__global__ void __launch_bounds__(256) k_qg(const float* __restrict__ x,
                                            const float* __restrict__ Wq,
                                            const float* __restrict__ Wk) {
    int b = blockIdx.x / Hh, h = blockIdx.x % Hh;
    __shared__ float xs[Rr * DIM];                  // 48KB
    const float* xb = x + (size_t)b * Nn * DIM;
    for (int i = threadIdx.x; i < Rr * DIM; i += 256) xs[i] = xb[i];
    __syncthreads();
    int warp = threadIdx.x >> 5, lane = threadIdx.x & 31;

    float qv[8];
    #pragma unroll 1
    for (int i = 0; i < 8; i++) {
        int d = warp * 8 + i;
        const float* wrow = Wq + (size_t)(h * HD + d) * DIM;
        float acc[8] = {0.f,0.f,0.f,0.f,0.f,0.f,0.f,0.f};
        for (int c = lane; c < DIM; c += 32) {
            float w = wrow[c];
            #pragma unroll
            for (int r = 0; r < 8; r++) acc[r] += w * xs[r * DIM + c];
        }
        #pragma unroll
        for (int r = 0; r < 8; r++)
            #pragma unroll
            for (int off = 16; off > 0; off >>= 1)
                acc[r] += __shfl_xor_sync(0xffffffffu, acc[r], off);
        qv[i] = (lane < 8) ? acc[lane] * SCALE : 0.f;
    }
    __syncthreads();
    if (lane < 8) {
        #pragma unroll
        for (int i = 0; i < 8; i++)
            xs[lane * HD + warp * 8 + i] = qv[i];    // qs[r][d]
    }
    __syncthreads();

    float acc[6][8];
    #pragma unroll
    for (int cc = 0; cc < 6; cc++)
        #pragma unroll
        for (int r = 0; r < 8; r++) acc[cc][r] = 0.f;
    const float* wbase = Wk + (size_t)(h * HD) * DIM;
    #pragma unroll 4
    for (int d = 0; d < HD; d++) {
        #pragma unroll
        for (int cc = 0; cc < 6; cc++) {
            int c = cc * 256 + threadIdx.x;
            float w = wbase[(size_t)d * DIM + c];
            #pragma unroll
            for (int r = 0; r < 8; r++) acc[cc][r] += xs[r * HD + d] * w;
        }
    }
    #pragma unroll
    for (int cc = 0; cc < 6; cc++)
        #pragma unroll
        for (int r = 0; r < 8; r++)
            g_G[((size_t)b * JH + h * Rr + r) * DIM + cc * 256 + threadIdx.x] = acc[cc][r];
}

// ============================================================================
// K2: partial S = G[:, kslab] @ x[:, kslab]^T   (tf32 wmma, cp.async, split-K)
// CTA 64(j) x 128(n), k-chunk 16, double buffered. 8 warps 2x4, warp 32x32.
// grid (32, 3, Bc*KSPS), 256 threads
// ============================================================================
#define LDK 20
#define KCS (DIM / KSPS / 16)   // 48 chunks per split
__global__ void __launch_bounds__(256) k_gemmS(const float* __restrict__ x) {
    __shared__ float As[2][64 * LDK];
    __shared__ float Bs[2][128 * LDK];
    int b = blockIdx.z >> 1, ks = blockIdx.z & 1;
    int koff = ks * (DIM / KSPS);
    int j0 = blockIdx.y * 64, n0 = blockIdx.x * 128;
    const float* Gb = g_G + ((size_t)b * JH + j0) * DIM + koff;
    const float* xb = x + ((size_t)b * Nn + n0) * DIM + koff;
    int tid = threadIdx.x;
    int warp = tid >> 5, wm = warp >> 2, wn = warp & 3;
    int arow = tid >> 2, akseg = (tid & 3) << 2;

    wmma::fragment<wmma::matrix_a, 16, 16, 8, wmma::precision::tf32, wmma::row_major> a0, a1;
    wmma::fragment<wmma::matrix_b, 16, 16, 8, wmma::precision::tf32, wmma::col_major> b0, b1;
    wmma::fragment<wmma::accumulator, 16, 16, 8, float> c[2][2];
    #pragma unroll
    for (int mi = 0; mi < 2; mi++)
        #pragma unroll
        for (int ni = 0; ni < 2; ni++) wmma::fill_fragment(c[mi][ni], 0.f);

    cp16(&As[0][arow * LDK + akseg], &Gb[(size_t)arow * DIM + akseg]);
    cp16(&Bs[0][arow * LDK + akseg], &xb[(size_t)arow * DIM + akseg]);
    cp16(&Bs[0][(arow + 64) * LDK + akseg], &xb[(size_t)(arow + 64) * DIM + akseg]);
    cp_commit();

    for (int kc = 0; kc < KCS; kc++) {
        if (kc + 1 < KCS) {
            int k0 = (kc + 1) << 4, nb = (kc + 1) & 1;
            cp16(&As[nb][arow * LDK + akseg], &Gb[(size_t)arow * DIM + k0 + akseg]);
            cp16(&Bs[nb][arow * LDK + akseg], &xb[(size_t)arow * DIM + k0 + akseg]);
            cp16(&Bs[nb][(arow + 64) * LDK + akseg], &xb[(size_t)(arow + 64) * DIM + k0 + akseg]);
            cp_commit();
            cp_wait<1>();
        } else {
            cp_wait<0>();
        }
        __syncthreads();
        int buf = kc & 1;
        #pragma unroll
        for (int kk = 0; kk < 16; kk += 8) {
            wmma::load_matrix_sync(a0, &As[buf][(wm * 32) * LDK + kk], LDK);
            wmma::load_matrix_sync(a1, &As[buf][(wm * 32 + 16) * LDK + kk], LDK);
            wmma::load_matrix_sync(b0, &Bs[buf][(wn * 32) * LDK + kk], LDK);
            wmma::load_matrix_sync(b1, &Bs[buf][(wn * 32 + 16) * LDK + kk], LDK);
            #pragma unroll
            for (int t = 0; t < a0.num_elements; t++) { a0.x[t] = wmma::__float_to_tf32(a0.x[t]); a1.x[t] = wmma::__float_to_tf32(a1.x[t]); }
            #pragma unroll
            for (int t = 0; t < b0.num_elements; t++) { b0.x[t] = wmma::__float_to_tf32(b0.x[t]); b1.x[t] = wmma::__float_to_tf32(b1.x[t]); }
            wmma::mma_sync(c[0][0], a0, b0, c[0][0]);
            wmma::mma_sync(c[0][1], a0, b1, c[0][1]);
            wmma::mma_sync(c[1][0], a1, b0, c[1][0]);
            wmma::mma_sync(c[1][1], a1, b1, c[1][1]);
        }
        __syncthreads();
    }
    float* Sb = g_Sp[ks] + (size_t)b * JH * Nn;
    #pragma unroll
    for (int mi = 0; mi < 2; mi++)
        #pragma unroll
        for (int ni = 0; ni < 2; ni++)
            wmma::store_matrix_sync(&Sb[(size_t)(j0 + wm * 32 + mi * 16) * Nn + n0 + wn * 32 + ni * 16],
                                    c[mi][ni], Nn, wmma::mem_row_major);
}

// ============================================================================
// K3: masked softmax; sums the 2 split-K partials on load. grid 1536, 256 thr
// ============================================================================
__global__ void __launch_bounds__(256) k_softmax(const int* __restrict__ mask) {
    int bj = blockIdx.x;
    int b = bj / JH, j = bj % JH, r = j % Rr;
    const float* p0 = g_Sp[0] + (size_t)bj * Nn;
    const float* p1 = g_Sp[1] + (size_t)bj * Nn;
    float* row = g_S + (size_t)bj * Nn;
    const int* mrow = mask + ((size_t)b * Rr + r) * MASKW;
    int tid = threadIdx.x, warp = tid >> 5, lane = tid & 31;
    __shared__ float red[8];

    float v[16];
    float mx = -3.0e38f;
    #pragma unroll
    for (int i = 0; i < 16; i++) {
        int n = tid + (i << 8);
        bool valid = (n < Rr) ? (n == r) : (mrow[n - Rr] != 0);
        v[i] = valid ? (p0[n] + p1[n]) : -3.0e38f;
        mx = fmaxf(mx, v[i]);
    }
    #pragma unroll
    for (int off = 16; off > 0; off >>= 1) mx = fmaxf(mx, __shfl_xor_sync(0xffffffffu, mx, off));
    if (lane == 0) red[warp] = mx;
    __syncthreads();
    if (warp == 0) {
        float t = (lane < 8) ? red[lane] : -3.0e38f;
        #pragma unroll
        for (int off = 4; off > 0; off >>= 1) t = fmaxf(t, __shfl_xor_sync(0xffffffffu, t, off));
        if (lane == 0) red[0] = t;
    }
    __syncthreads();
    mx = red[0];
    __syncthreads();

    float sum = 0.f;
    #pragma unroll
    for (int i = 0; i < 16; i++) {
        v[i] = __expf(v[i] - mx);
        sum += v[i];
    }
    #pragma unroll
    for (int off = 16; off > 0; off >>= 1) sum += __shfl_xor_sync(0xffffffffu, sum, off);
    if (lane == 0) red[warp] = sum;
    __syncthreads();
    if (warp == 0) {
        float t = (lane < 8) ? red[lane] : 0.f;
        #pragma unroll
        for (int off = 4; off > 0; off >>= 1) t += __shfl_xor_sync(0xffffffffu, t, off);
        if (lane == 0) red[0] = t;
    }
    __syncthreads();
    float inv = 1.f / red[0];
    #pragma unroll
    for (int i = 0; i < 16; i++) row[tid + (i << 8)] = v[i] * inv;
}

// ============================================================================
// K4: partial Y = P[:, kslab] @ x[kslab, :]  (tf32 wmma, cp.async, split-K)
// CTA 64(j) x 128(c), k-chunk 16, double buffered. grid (12, 3, Bc*KSPY)
// ============================================================================
#define LDC 132
#define KCY (Nn / KSPY / 16)    // 64 chunks per split
__global__ void __launch_bounds__(256) k_gemmY(const float* __restrict__ x) {
    __shared__ float As[2][64 * LDK];
    __shared__ float Bs[2][16 * LDC];
    int b = blockIdx.z >> 2, ks = blockIdx.z & 3;
    int koff = ks * (Nn / KSPY);
    int j0 = blockIdx.y * 64, c0 = blockIdx.x * 128;
    const float* Pb = g_S + ((size_t)b * JH + j0) * Nn + koff;
    const float* xb = x + ((size_t)b * Nn + koff) * DIM;
    int tid = threadIdx.x;
    int warp = tid >> 5, wm = warp >> 2, wn = warp & 3;
    int arow = tid >> 2, akseg = (tid & 3) << 2;
    int brow = tid >> 5, bcseg = (tid & 31) << 2;

    wmma::fragment<wmma::matrix_a, 16, 16, 8, wmma::precision::tf32, wmma::row_major> a0, a1;
    wmma::fragment<wmma::matrix_b, 16, 16, 8, wmma::precision::tf32, wmma::row_major> b0, b1;
    wmma::fragment<wmma::accumulator, 16, 16, 8, float> c[2][2];
    #pragma unroll
    for (int mi = 0; mi < 2; mi++)
        #pragma unroll
        for (int ni = 0; ni < 2; ni++) wmma::fill_fragment(c[mi][ni], 0.f);

    cp16(&As[0][arow * LDK + akseg], &Pb[(size_t)arow * Nn + akseg]);
    cp16(&Bs[0][brow * LDC + bcseg], &xb[(size_t)brow * DIM + c0 + bcseg]);
    cp16(&Bs[0][(brow + 8) * LDC + bcseg], &xb[(size_t)(brow + 8) * DIM + c0 + bcseg]);
    cp_commit();

    for (int kc = 0; kc < KCY; kc++) {
        if (kc + 1 < KCY) {
            int k0 = (kc + 1) << 4, nb = (kc + 1) & 1;
            cp16(&As[nb][arow * LDK + akseg], &Pb[(size_t)arow * Nn + k0 + akseg]);
            cp16(&Bs[nb][brow * LDC + bcseg], &xb[(size_t)(k0 + brow) * DIM + c0 + bcseg]);
            cp16(&Bs[nb][(brow + 8) * LDC + bcseg], &xb[(size_t)(k0 + brow + 8) * DIM + c0 + bcseg]);
            cp_commit();
            cp_wait<1>();
        } else {
            cp_wait<0>();
        }
        __syncthreads();
        int buf = kc & 1;
        #pragma unroll
        for (int kk = 0; kk < 16; kk += 8) {
            wmma::load_matrix_sync(a0, &As[buf][(wm * 32) * LDK + kk], LDK);
            wmma::load_matrix_sync(a1, &As[buf][(wm * 32 + 16) * LDK + kk], LDK);
            wmma::load_matrix_sync(b0, &Bs[buf][kk * LDC + wn * 32], LDC);
            wmma::load_matrix_sync(b1, &Bs[buf][kk * LDC + wn * 32 + 16], LDC);
            #pragma unroll
            for (int t = 0; t < a0.num_elements; t++) { a0.x[t] = wmma::__float_to_tf32(a0.x[t]); a1.x[t] = wmma::__float_to_tf32(a1.x[t]); }
            #pragma unroll
            for (int t = 0; t < b0.num_elements; t++) { b0.x[t] = wmma::__float_to_tf32(b0.x[t]); b1.x[t] = wmma::__float_to_tf32(b1.x[t]); }
            wmma::mma_sync(c[0][0], a0, b0, c[0][0]);
            wmma::mma_sync(c[0][1], a0, b1, c[0][1]);
            wmma::mma_sync(c[1][0], a1, b0, c[1][0]);
            wmma::mma_sync(c[1][1], a1, b1, c[1][1]);
        }
        __syncthreads();
    }
    float* Yb = g_Yp[ks] + (size_t)b * JH * DIM;
    #pragma unroll
    for (int mi = 0; mi < 2; mi++)
        #pragma unroll
        for (int ni = 0; ni < 2; ni++)
            wmma::store_matrix_sync(&Yb[(size_t)(j0 + wm * 32 + mi * 16) * DIM + c0 + wn * 32 + ni * 16],
                                    c[mi][ni], DIM, wmma::mem_row_major);
}

// ============================================================================
// K5a: reduce 4 Y partials + x_cls[b][r][e] = sum_c Y[b][h*8+r][c] * Wv[e][c]
// grid 192 = (b,h), 256 threads
// ============================================================================
__global__ void __launch_bounds__(256) k_xcls(const float* __restrict__ Wv) {
    int b = blockIdx.x / Hh, h = blockIdx.x % Hh;
    __shared__ float Ys[Rr * DIM];
    size_t base = ((size_t)b * JH + h * Rr) * DIM;
    for (int i = threadIdx.x; i < Rr * DIM; i += 256)
        Ys[i] = g_Yp[0][base + i] + g_Yp[1][base + i] + g_Yp[2][base + i] + g_Yp[3][base + i];
    __syncthreads();
    int warp = threadIdx.x >> 5, lane = threadIdx.x & 31;
    #pragma unroll 1
    for (int i = 0; i < 8; i++) {
        int e = h * HD + warp * 8 + i;
        const float* wrow = Wv + (size_t)e * DIM;
        float acc[8] = {0.f,0.f,0.f,0.f,0.f,0.f,0.f,0.f};
        for (int c = lane; c < DIM; c += 32) {
            float w = wrow[c];
            #pragma unroll
            for (int r = 0; r < 8; r++) acc[r] += w * Ys[r * DIM + c];
        }
        #pragma unroll
        for (int r = 0; r < 8; r++)
            #pragma unroll
            for (int off = 16; off > 0; off >>= 1)
                acc[r] += __shfl_xor_sync(0xffffffffu, acc[r], off);
        if (lane < 8)
            g_xcls[((size_t)b * Rr + lane) * DIM + e] = acc[lane];
    }
}

// ============================================================================
// K5b: out[b][r][o] = dot(x_cls[b][r][:], Wp[o][:]) + bp[o]
// grid 192, 256 threads
// ============================================================================
__global__ void __launch_bounds__(256) k_out(const float* __restrict__ Wp,
                                             const float* __restrict__ bp,
                                             float* __restrict__ out) {
    int b = blockIdx.x / Hh, oblk = blockIdx.x % Hh;
    __shared__ float xcs[Rr * DIM];
    for (int i = threadIdx.x; i < Rr * DIM; i += 256)
        xcs[i] = g_xcls[(size_t)b * Rr * DIM + i];
    __syncthreads();
    int warp = threadIdx.x >> 5, lane = threadIdx.x & 31;
    #pragma unroll 1
    for (int i = 0; i < 8; i++) {
        int o = oblk * HD + warp * 8 + i;
        const float* wrow = Wp + (size_t)o * DIM;
        float acc[8] = {0.f,0.f,0.f,0.f,0.f,0.f,0.f,0.f};
        for (int c = lane; c < DIM; c += 32) {
            float w = wrow[c];
            #pragma unroll
            for (int r = 0; r < 8; r++) acc[r] += w * xcs[r * DIM + c];
        }
        #pragma unroll
        for (int r = 0; r < 8; r++)
            #pragma unroll
            for (int off = 16; off > 0; off >>= 1)
                acc[r] += __shfl_xor_sync(0xffffffffu, acc[r], off);
        if (lane < 8)
            out[((size_t)b * Rr + lane) * DIM + o] = acc[lane] + bp[o];
    }
}

// ============================================================================
extern "C" void kernel_launch(void* const* d_in, const int* in_sizes, int n_in,
                              void* d_out, int out_size) {
    const float* x    = (const float*)d_in[0];
    const int*   mask = (const int*)d_in[1];
    const float* Wq   = (const float*)d_in[2];
    const float* Wk   = (const float*)d_in[3];
    const float* Wv   = (const float*)d_in[4];
    const float* Wp   = (const float*)d_in[5];
    const float* bp   = (const float*)d_in[6];
    float*       out  = (float*)d_out;

    k_qg     <<<Bc * Hh, 256>>>(x, Wq, Wk);
    k_gemmS  <<<dim3(Nn / 128, JH / 64, Bc * KSPS), 256>>>(x);
    k_softmax<<<Bc * JH, 256>>>(mask);
    k_gemmY  <<<dim3(DIM / 128, JH / 64, Bc * KSPY), 256>>>(x);
    k_xcls   <<<Bc * Hh, 256>>>(Wv);
    k_out    <<<Bc * Hh, 256>>>(Wp, bp, out);
}

// round 6
// speedup vs baseline: 2.8916x; 2.0246x over previous
#include <cuda_runtime.h>
#include <cuda_fp16.h>
#include <mma.h>
#include <cstdint>

using namespace nvcuda;

// Problem constants
#define Bc   8
#define Nn   4096
#define DIM  1536
#define Hh   24
#define HD   64
#define Rr   8
#define JH   192
#define SCALE 0.125f
#define MASKW (Nn - Rr)

#define KSPS 2                  // split-K for S (768 per split)
#define KSPY 4                  // split-K for Y (1024 per split)

// ---------------- scratch ----------------
__device__ __half g_Gh[Bc * JH * DIM];                  // [b][j][c] half
__device__ __half g_xh[(size_t)Bc * Nn * DIM];          // half copy of x
__device__ float  g_Sp[KSPS][(size_t)Bc * JH * Nn];     // partial logits (fp32)
__device__ __half g_Sh[(size_t)Bc * JH * Nn];           // probs (half)
__device__ float  g_Yp[KSPY][Bc * JH * DIM];            // partial Y (fp32)
__device__ float  g_xcls[Bc * Rr * DIM];

// ---------------- cp.async helpers ----------------
__device__ __forceinline__ void cp16(void* s, const void* g) {
    uint32_t sa = (uint32_t)__cvta_generic_to_shared(s);
    asm volatile("cp.async.ca.shared.global [%0], [%1], 16;" :: "r"(sa), "l"(g));
}
__device__ __forceinline__ void cp_commit() { asm volatile("cp.async.commit_group;"); }
template<int N> __device__ __forceinline__ void cp_wait() {
    asm volatile("cp.async.wait_group %0;" :: "n"(N));
}

// ============================================================================
// K0: g_xh = half(x)  — vectorized convert, 8 floats/thread
// ============================================================================
__global__ void __launch_bounds__(256) k_xh(const float* __restrict__ x) {
    size_t i = ((size_t)blockIdx.x * 256 + threadIdx.x) * 8;
    float4 v0 = *(const float4*)&x[i];
    float4 v1 = *(const float4*)&x[i + 4];
    __half2 h[4];
    h[0] = __floats2half2_rn(v0.x, v0.y);
    h[1] = __floats2half2_rn(v0.z, v0.w);
    h[2] = __floats2half2_rn(v1.x, v1.y);
    h[3] = __floats2half2_rn(v1.z, v1.w);
    *(uint4*)&g_xh[i] = *(uint4*)h;
}

// ============================================================================
// K1 (fused): q = SCALE * x[:8] @ Wq_h^T ; G[j] = half(q @ Wk_h)
// grid 192 = (b,h), 256 threads
// ============================================================================
__global__ void __launch_bounds__(256) k_qg(const float* __restrict__ x,
                                            const float* __restrict__ Wq,
                                            const float* __restrict__ Wk) {
    int b = blockIdx.x / Hh, h = blockIdx.x % Hh;
    __shared__ float xs[Rr * DIM];
    const float* xb = x + (size_t)b * Nn * DIM;
    for (int i = threadIdx.x; i < Rr * DIM; i += 256) xs[i] = xb[i];
    __syncthreads();
    int warp = threadIdx.x >> 5, lane = threadIdx.x & 31;

    float qv[8];
    #pragma unroll 1
    for (int i = 0; i < 8; i++) {
        int d = warp * 8 + i;
        const float* wrow = Wq + (size_t)(h * HD + d) * DIM;
        float acc[8] = {0.f,0.f,0.f,0.f,0.f,0.f,0.f,0.f};
        for (int c = lane; c < DIM; c += 32) {
            float w = wrow[c];
            #pragma unroll
            for (int r = 0; r < 8; r++) acc[r] += w * xs[r * DIM + c];
        }
        #pragma unroll
        for (int r = 0; r < 8; r++)
            #pragma unroll
            for (int off = 16; off > 0; off >>= 1)
                acc[r] += __shfl_xor_sync(0xffffffffu, acc[r], off);
        qv[i] = (lane < 8) ? acc[lane] * SCALE : 0.f;
    }
    __syncthreads();
    if (lane < 8) {
        #pragma unroll
        for (int i = 0; i < 8; i++) xs[lane * HD + warp * 8 + i] = qv[i];
    }
    __syncthreads();

    float acc[6][8];
    #pragma unroll
    for (int cc = 0; cc < 6; cc++)
        #pragma unroll
        for (int r = 0; r < 8; r++) acc[cc][r] = 0.f;
    const float* wbase = Wk + (size_t)(h * HD) * DIM;
    #pragma unroll 4
    for (int d = 0; d < HD; d++) {
        #pragma unroll
        for (int cc = 0; cc < 6; cc++) {
            int c = cc * 256 + threadIdx.x;
            float w = wbase[(size_t)d * DIM + c];
            #pragma unroll
            for (int r = 0; r < 8; r++) acc[cc][r] += xs[r * HD + d] * w;
        }
    }
    #pragma unroll
    for (int cc = 0; cc < 6; cc++)
        #pragma unroll
        for (int r = 0; r < 8; r++)
            g_Gh[((size_t)b * JH + h * Rr + r) * DIM + cc * 256 + threadIdx.x] =
                __float2half_rn(acc[cc][r]);
}

// ============================================================================
// K2: partial S = Gh[:, slab] @ xh[:, slab]^T   (fp16 wmma m16n16k16)
// CTA 64(j) x 128(n), k-chunk 32, double buffered. 8 warps 2x4, warp 32x32.
// grid (32, 3, Bc*KSPS), 256 threads
// ============================================================================
#define LDH 40     // half stride (32 + 8 pad)
#define KCS (DIM / KSPS / 32)   // 24 chunks
__global__ void __launch_bounds__(256) k_gemmS(int dummy) {
    __shared__ __half As[2][64 * LDH];
    __shared__ __half Bs[2][128 * LDH];
    int b = blockIdx.z >> 1, ks = blockIdx.z & 1;
    int koff = ks * (DIM / KSPS);
    int j0 = blockIdx.y * 64, n0 = blockIdx.x * 128;
    const __half* Ag = g_Gh + ((size_t)b * JH + j0) * DIM + koff;
    const __half* Bg = g_xh + ((size_t)b * Nn + n0) * DIM + koff;
    int tid = threadIdx.x;
    int warp = tid >> 5, wm = warp >> 2, wn = warp & 3;
    int arow = tid >> 2, aseg = (tid & 3) << 3;      // 64 rows x 4 segs of 8 halves

    wmma::fragment<wmma::matrix_a, 16, 16, 16, __half, wmma::row_major> a0, a1;
    wmma::fragment<wmma::matrix_b, 16, 16, 16, __half, wmma::col_major> b0, b1;
    wmma::fragment<wmma::accumulator, 16, 16, 16, float> c[2][2];
    #pragma unroll
    for (int mi = 0; mi < 2; mi++)
        #pragma unroll
        for (int ni = 0; ni < 2; ni++) wmma::fill_fragment(c[mi][ni], 0.f);

    // prefetch chunk 0
    cp16(&As[0][arow * LDH + aseg], &Ag[(size_t)arow * DIM + aseg]);
    cp16(&Bs[0][arow * LDH + aseg], &Bg[(size_t)arow * DIM + aseg]);
    cp16(&Bs[0][(arow + 64) * LDH + aseg], &Bg[(size_t)(arow + 64) * DIM + aseg]);
    cp_commit();

    for (int kc = 0; kc < KCS; kc++) {
        if (kc + 1 < KCS) {
            int k0 = (kc + 1) << 5, nb = (kc + 1) & 1;
            cp16(&As[nb][arow * LDH + aseg], &Ag[(size_t)arow * DIM + k0 + aseg]);
            cp16(&Bs[nb][arow * LDH + aseg], &Bg[(size_t)arow * DIM + k0 + aseg]);
            cp16(&Bs[nb][(arow + 64) * LDH + aseg], &Bg[(size_t)(arow + 64) * DIM + k0 + aseg]);
            cp_commit();
            cp_wait<1>();
        } else {
            cp_wait<0>();
        }
        __syncthreads();
        int buf = kc & 1;
        #pragma unroll
        for (int kk = 0; kk < 32; kk += 16) {
            wmma::load_matrix_sync(a0, &As[buf][(wm * 32) * LDH + kk], LDH);
            wmma::load_matrix_sync(a1, &As[buf][(wm * 32 + 16) * LDH + kk], LDH);
            wmma::load_matrix_sync(b0, &Bs[buf][(wn * 32) * LDH + kk], LDH);
            wmma::load_matrix_sync(b1, &Bs[buf][(wn * 32 + 16) * LDH + kk], LDH);
            wmma::mma_sync(c[0][0], a0, b0, c[0][0]);
            wmma::mma_sync(c[0][1], a0, b1, c[0][1]);
            wmma::mma_sync(c[1][0], a1, b0, c[1][0]);
            wmma::mma_sync(c[1][1], a1, b1, c[1][1]);
        }
        __syncthreads();
    }
    float* Sb = g_Sp[ks] + (size_t)b * JH * Nn;
    #pragma unroll
    for (int mi = 0; mi < 2; mi++)
        #pragma unroll
        for (int ni = 0; ni < 2; ni++)
            wmma::store_matrix_sync(&Sb[(size_t)(j0 + wm * 32 + mi * 16) * Nn + n0 + wn * 32 + ni * 16],
                                    c[mi][ni], Nn, wmma::mem_row_major);
}

// ============================================================================
// K3: masked softmax; sums 2 partials, writes half probs. grid 1536, 256 thr
// ============================================================================
__global__ void __launch_bounds__(256) k_softmax(const int* __restrict__ mask) {
    int bj = blockIdx.x;
    int b = bj / JH, j = bj % JH, r = j % Rr;
    const float* p0 = g_Sp[0] + (size_t)bj * Nn;
    const float* p1 = g_Sp[1] + (size_t)bj * Nn;
    __half* row = g_Sh + (size_t)bj * Nn;
    const int* mrow = mask + ((size_t)b * Rr + r) * MASKW;
    int tid = threadIdx.x, warp = tid >> 5, lane = tid & 31;
    __shared__ float red[8];

    float v[16];
    float mx = -3.0e38f;
    #pragma unroll
    for (int i = 0; i < 16; i++) {
        int n = tid + (i << 8);
        bool valid = (n < Rr) ? (n == r) : (mrow[n - Rr] != 0);
        v[i] = valid ? (p0[n] + p1[n]) : -3.0e38f;
        mx = fmaxf(mx, v[i]);
    }
    #pragma unroll
    for (int off = 16; off > 0; off >>= 1) mx = fmaxf(mx, __shfl_xor_sync(0xffffffffu, mx, off));
    if (lane == 0) red[warp] = mx;
    __syncthreads();
    if (warp == 0) {
        float t = (lane < 8) ? red[lane] : -3.0e38f;
        #pragma unroll
        for (int off = 4; off > 0; off >>= 1) t = fmaxf(t, __shfl_xor_sync(0xffffffffu, t, off));
        if (lane == 0) red[0] = t;
    }
    __syncthreads();
    mx = red[0];
    __syncthreads();

    float sum = 0.f;
    #pragma unroll
    for (int i = 0; i < 16; i++) { v[i] = __expf(v[i] - mx); sum += v[i]; }
    #pragma unroll
    for (int off = 16; off > 0; off >>= 1) sum += __shfl_xor_sync(0xffffffffu, sum, off);
    if (lane == 0) red[warp] = sum;
    __syncthreads();
    if (warp == 0) {
        float t = (lane < 8) ? red[lane] : 0.f;
        #pragma unroll
        for (int off = 4; off > 0; off >>= 1) t += __shfl_xor_sync(0xffffffffu, t, off);
        if (lane == 0) red[0] = t;
    }
    __syncthreads();
    float inv = 1.f / red[0];
    #pragma unroll
    for (int i = 0; i < 16; i++)
        row[tid + (i << 8)] = __float2half_rn(v[i] * inv);
}

// ============================================================================
// K4: partial Y = Ph[:, slab] @ xh[slab, :]  (fp16 wmma m16n16k16)
// CTA 64(j) x 128(c), k-chunk 32, double buffered. grid (12, 3, Bc*KSPY)
// ============================================================================
#define LDC2 136   // half stride for B tile (128 + 8 pad)
#define KCY (Nn / KSPY / 32)    // 32 chunks
__global__ void __launch_bounds__(256) k_gemmY(int dummy) {
    __shared__ __half As[2][64 * LDH];
    __shared__ __half Bs[2][32 * LDC2];
    int b = blockIdx.z >> 2, ks = blockIdx.z & 3;
    int koff = ks * (Nn / KSPY);
    int j0 = blockIdx.y * 64, c0 = blockIdx.x * 128;
    const __half* Ag = g_Sh + ((size_t)b * JH + j0) * Nn + koff;
    const __half* Bg = g_xh + ((size_t)b * Nn + koff) * DIM;
    int tid = threadIdx.x;
    int warp = tid >> 5, wm = warp >> 2, wn = warp & 3;
    int arow = tid >> 2, aseg = (tid & 3) << 3;      // A: 64 rows x 4 segs
    int brow = tid >> 4, bseg = (tid & 15) << 3;     // B: 16 rows x 16 segs (x2)

    wmma::fragment<wmma::matrix_a, 16, 16, 16, __half, wmma::row_major> a0, a1;
    wmma::fragment<wmma::matrix_b, 16, 16, 16, __half, wmma::row_major> b0, b1;
    wmma::fragment<wmma::accumulator, 16, 16, 16, float> c[2][2];
    #pragma unroll
    for (int mi = 0; mi < 2; mi++)
        #pragma unroll
        for (int ni = 0; ni < 2; ni++) wmma::fill_fragment(c[mi][ni], 0.f);

    cp16(&As[0][arow * LDH + aseg], &Ag[(size_t)arow * Nn + aseg]);
    cp16(&Bs[0][brow * LDC2 + bseg], &Bg[(size_t)brow * DIM + c0 + bseg]);
    cp16(&Bs[0][(brow + 16) * LDC2 + bseg], &Bg[(size_t)(brow + 16) * DIM + c0 + bseg]);
    cp_commit();

    for (int kc = 0; kc < KCY; kc++) {
        if (kc + 1 < KCY) {
            int k0 = (kc + 1) << 5, nb = (kc + 1) & 1;
            cp16(&As[nb][arow * LDH + aseg], &Ag[(size_t)arow * Nn + k0 + aseg]);
            cp16(&Bs[nb][brow * LDC2 + bseg], &Bg[(size_t)(k0 + brow) * DIM + c0 + bseg]);
            cp16(&Bs[nb][(brow + 16) * LDC2 + bseg], &Bg[(size_t)(k0 + brow + 16) * DIM + c0 + bseg]);
            cp_commit();
            cp_wait<1>();
        } else {
            cp_wait<0>();
        }
        __syncthreads();
        int buf = kc & 1;
        #pragma unroll
        for (int kk = 0; kk < 32; kk += 16) {
            wmma::load_matrix_sync(a0, &As[buf][(wm * 32) * LDH + kk], LDH);
            wmma::load_matrix_sync(a1, &As[buf][(wm * 32 + 16) * LDH + kk], LDH);
            wmma::load_matrix_sync(b0, &Bs[buf][kk * LDC2 + wn * 32], LDC2);
            wmma::load_matrix_sync(b1, &Bs[buf][kk * LDC2 + wn * 32 + 16], LDC2);
            wmma::mma_sync(c[0][0], a0, b0, c[0][0]);
            wmma::mma_sync(c[0][1], a0, b1, c[0][1]);
            wmma::mma_sync(c[1][0], a1, b0, c[1][0]);
            wmma::mma_sync(c[1][1], a1, b1, c[1][1]);
        }
        __syncthreads();
    }
    float* Yb = g_Yp[ks] + (size_t)b * JH * DIM;
    #pragma unroll
    for (int mi = 0; mi < 2; mi++)
        #pragma unroll
        for (int ni = 0; ni < 2; ni++)
            wmma::store_matrix_sync(&Yb[(size_t)(j0 + wm * 32 + mi * 16) * DIM + c0 + wn * 32 + ni * 16],
                                    c[mi][ni], DIM, wmma::mem_row_major);
}

// ============================================================================
// K5a: reduce 4 Y partials + x_cls[b][r][e] = sum_c Y[b][h*8+r][c] * Wv[e][c]
// ============================================================================
__global__ void __launch_bounds__(256) k_xcls(const float* __restrict__ Wv) {
    int b = blockIdx.x / Hh, h = blockIdx.x % Hh;
    __shared__ float Ys[Rr * DIM];
    size_t base = ((size_t)b * JH + h * Rr) * DIM;
    for (int i = threadIdx.x; i < Rr * DIM; i += 256)
        Ys[i] = g_Yp[0][base + i] + g_Yp[1][base + i] + g_Yp[2][base + i] + g_Yp[3][base + i];
    __syncthreads();
    int warp = threadIdx.x >> 5, lane = threadIdx.x & 31;
    #pragma unroll 1
    for (int i = 0; i < 8; i++) {
        int e = h * HD + warp * 8 + i;
        const float* wrow = Wv + (size_t)e * DIM;
        float acc[8] = {0.f,0.f,0.f,0.f,0.f,0.f,0.f,0.f};
        for (int c = lane; c < DIM; c += 32) {
            float w = wrow[c];
            #pragma unroll
            for (int r = 0; r < 8; r++) acc[r] += w * Ys[r * DIM + c];
        }
        #pragma unroll
        for (int r = 0; r < 8; r++)
            #pragma unroll
            for (int off = 16; off > 0; off >>= 1)
                acc[r] += __shfl_xor_sync(0xffffffffu, acc[r], off);
        if (lane < 8)
            g_xcls[((size_t)b * Rr + lane) * DIM + e] = acc[lane];
    }
}

// ============================================================================
// K5b: out[b][r][o] = dot(x_cls[b][r][:], Wp[o][:]) + bp[o]
// ============================================================================
__global__ void __launch_bounds__(256) k_out(const float* __restrict__ Wp,
                                             const float* __restrict__ bp,
                                             float* __restrict__ out) {
    int b = blockIdx.x / Hh, oblk = blockIdx.x % Hh;
    __shared__ float xcs[Rr * DIM];
    for (int i = threadIdx.x; i < Rr * DIM; i += 256)
        xcs[i] = g_xcls[(size_t)b * Rr * DIM + i];
    __syncthreads();
    int warp = threadIdx.x >> 5, lane = threadIdx.x & 31;
    #pragma unroll 1
    for (int i = 0; i < 8; i++) {
        int o = oblk * HD + warp * 8 + i;
        const float* wrow = Wp + (size_t)o * DIM;
        float acc[8] = {0.f,0.f,0.f,0.f,0.f,0.f,0.f,0.f};
        for (int c = lane; c < DIM; c += 32) {
            float w = wrow[c];
            #pragma unroll
            for (int r = 0; r < 8; r++) acc[r] += w * xcs[r * DIM + c];
        }
        #pragma unroll
        for (int r = 0; r < 8; r++)
            #pragma unroll
            for (int off = 16; off > 0; off >>= 1)
                acc[r] += __shfl_xor_sync(0xffffffffu, acc[r], off);
        if (lane < 8)
            out[((size_t)b * Rr + lane) * DIM + o] = acc[lane] + bp[o];
    }
}

// ============================================================================
extern "C" void kernel_launch(void* const* d_in, const int* in_sizes, int n_in,
                              void* d_out, int out_size) {
    const float* x    = (const float*)d_in[0];
    const int*   mask = (const int*)d_in[1];
    const float* Wq   = (const float*)d_in[2];
    const float* Wk   = (const float*)d_in[3];
    const float* Wv   = (const float*)d_in[4];
    const float* Wp   = (const float*)d_in[5];
    const float* bp   = (const float*)d_in[6];
    float*       out  = (float*)d_out;

    k_xh     <<<(int)(((size_t)Bc * Nn * DIM) / (256 * 8)), 256>>>(x);
    k_qg     <<<Bc * Hh, 256>>>(x, Wq, Wk);
    k_gemmS  <<<dim3(Nn / 128, JH / 64, Bc * KSPS), 256>>>(0);
    k_softmax<<<Bc * JH, 256>>>(mask);
    k_gemmY  <<<dim3(DIM / 128, JH / 64, Bc * KSPY), 256>>>(0);
    k_xcls   <<<Bc * Hh, 256>>>(Wv);
    k_out    <<<Bc * Hh, 256>>>(Wp, bp, out);
}

// round 7
// speedup vs baseline: 3.0583x; 1.0576x over previous
#include <cuda_runtime.h>
#include <cuda_fp16.h>
#include <mma.h>
#include <cstdint>

using namespace nvcuda;

// Problem constants
#define Bc   8
#define Nn   4096
#define DIM  1536
#define Hh   24
#define HD   64
#define Rr   8
#define JH   192
#define SCALE 0.125f
#define MASKW (Nn - Rr)

#define KSPS 2                  // split-K for S (768 per split)
#define KSPY 4                  // split-K for Y (1024 per split)

// ---------------- scratch ----------------
__device__ __half g_Gh[Bc * JH * DIM];                  // [b][j][c] half
__device__ __half g_xh[(size_t)Bc * Nn * DIM];          // half copy of x
__device__ float  g_Sp[KSPS][(size_t)Bc * JH * Nn];     // partial logits (fp32)
__device__ __half g_Sh[(size_t)Bc * JH * Nn];           // probs (half)
__device__ float  g_Yp[KSPY][Bc * JH * DIM];            // partial Y (fp32)
__device__ float  g_xcls[Bc * Rr * DIM];

// ---------------- cp.async helpers ----------------
__device__ __forceinline__ void cp16(void* s, const void* g) {
    uint32_t sa = (uint32_t)__cvta_generic_to_shared(s);
    asm volatile("cp.async.ca.shared.global [%0], [%1], 16;" :: "r"(sa), "l"(g));
}
__device__ __forceinline__ void cp_commit() { asm volatile("cp.async.commit_group;"); }
template<int N> __device__ __forceinline__ void cp_wait() {
    asm volatile("cp.async.wait_group %0;" :: "n"(N));
}

// ============================================================================
// K0: g_xh = half(x)  — vectorized convert, 8 floats/thread
// ============================================================================
__global__ void __launch_bounds__(256) k_xh(const float* __restrict__ x) {
    size_t i = ((size_t)blockIdx.x * 256 + threadIdx.x) * 8;
    float4 v0 = *(const float4*)&x[i];
    float4 v1 = *(const float4*)&x[i + 4];
    __half2 h[4];
    h[0] = __floats2half2_rn(v0.x, v0.y);
    h[1] = __floats2half2_rn(v0.z, v0.w);
    h[2] = __floats2half2_rn(v1.x, v1.y);
    h[3] = __floats2half2_rn(v1.z, v1.w);
    *(uint4*)&g_xh[i] = *(uint4*)h;
}

// ============================================================================
// K1 (fused): q = SCALE * x[:8] @ Wq_h^T ; G[j] = half(q @ Wk_h)
// grid 192 = (b,h), 256 threads
// ============================================================================
__global__ void __launch_bounds__(256) k_qg(const float* __restrict__ x,
                                            const float* __restrict__ Wq,
                                            const float* __restrict__ Wk) {
    int b = blockIdx.x / Hh, h = blockIdx.x % Hh;
    __shared__ float xs[Rr * DIM];
    const float* xb = x + (size_t)b * Nn * DIM;
    for (int i = threadIdx.x; i < Rr * DIM; i += 256) xs[i] = xb[i];
    __syncthreads();
    int warp = threadIdx.x >> 5, lane = threadIdx.x & 31;

    float qv[8];
    #pragma unroll 1
    for (int i = 0; i < 8; i++) {
        int d = warp * 8 + i;
        const float* wrow = Wq + (size_t)(h * HD + d) * DIM;
        float acc[8] = {0.f,0.f,0.f,0.f,0.f,0.f,0.f,0.f};
        for (int c = lane; c < DIM; c += 32) {
            float w = wrow[c];
            #pragma unroll
            for (int r = 0; r < 8; r++) acc[r] += w * xs[r * DIM + c];
        }
        #pragma unroll
        for (int r = 0; r < 8; r++)
            #pragma unroll
            for (int off = 16; off > 0; off >>= 1)
                acc[r] += __shfl_xor_sync(0xffffffffu, acc[r], off);
        qv[i] = (lane < 8) ? acc[lane] * SCALE : 0.f;
    }
    __syncthreads();
    if (lane < 8) {
        #pragma unroll
        for (int i = 0; i < 8; i++) xs[lane * HD + warp * 8 + i] = qv[i];
    }
    __syncthreads();

    float acc[6][8];
    #pragma unroll
    for (int cc = 0; cc < 6; cc++)
        #pragma unroll
        for (int r = 0; r < 8; r++) acc[cc][r] = 0.f;
    const float* wbase = Wk + (size_t)(h * HD) * DIM;
    #pragma unroll 4
    for (int d = 0; d < HD; d++) {
        #pragma unroll
        for (int cc = 0; cc < 6; cc++) {
            int c = cc * 256 + threadIdx.x;
            float w = wbase[(size_t)d * DIM + c];
            #pragma unroll
            for (int r = 0; r < 8; r++) acc[cc][r] += xs[r * HD + d] * w;
        }
    }
    #pragma unroll
    for (int cc = 0; cc < 6; cc++)
        #pragma unroll
        for (int r = 0; r < 8; r++)
            g_Gh[((size_t)b * JH + h * Rr + r) * DIM + cc * 256 + threadIdx.x] =
                __float2half_rn(acc[cc][r]);
}

// ============================================================================
// K2: partial S = Gh[:, slab] @ xh[:, slab]^T   (fp16 wmma m16n16k16)
// CTA 64(j) x 256(n), k-chunk 32, 3-stage cp.async. 8 warps 2x4, warp 32x64.
// grid (16, 3, Bc*KSPS), 256 threads, dynamic smem
// ============================================================================
#define LDH 40                            // half stride (32 + 8 pad)
#define SA_H (64 * LDH)                   // 2560 halves / stage
#define SBS_H (256 * LDH)                 // 10240 halves / stage
#define SMEM_S ((3 * (SA_H + SBS_H)) * 2) // 76800 B
#define KCS (DIM / KSPS / 32)             // 24 chunks
__global__ void __launch_bounds__(256) k_gemmS(int dummy) {
    extern __shared__ __half sm[];
    __half* As = sm;                       // 3 stages
    __half* Bs = sm + 3 * SA_H;
    int b = blockIdx.z >> 1, ks = blockIdx.z & 1;
    int koff = ks * (DIM / KSPS);
    int j0 = blockIdx.y * 64, n0 = blockIdx.x * 256;
    const __half* Ag = g_Gh + ((size_t)b * JH + j0) * DIM + koff;
    const __half* Bg = g_xh + ((size_t)b * Nn + n0) * DIM + koff;
    int tid = threadIdx.x;
    int warp = tid >> 5, wm = warp >> 2, wn = warp & 3;
    int arow = tid >> 2, aseg = (tid & 3) << 3;      // A: 64 rows x 4 segs of 8 halves

    wmma::fragment<wmma::matrix_a, 16, 16, 16, __half, wmma::row_major> a0, a1;
    wmma::fragment<wmma::matrix_b, 16, 16, 16, __half, wmma::col_major> bf[4];
    wmma::fragment<wmma::accumulator, 16, 16, 16, float> c[2][4];
    #pragma unroll
    for (int mi = 0; mi < 2; mi++)
        #pragma unroll
        for (int ni = 0; ni < 4; ni++) wmma::fill_fragment(c[mi][ni], 0.f);

    auto prefetch = [&](int kc) {
        int s = kc % 3, k0 = kc << 5;
        cp16(&As[s * SA_H + arow * LDH + aseg], &Ag[(size_t)arow * DIM + k0 + aseg]);
        #pragma unroll
        for (int p = 0; p < 4; p++) {
            int i = tid + p * 256; int row = i >> 2, seg = (i & 3) << 3;
            cp16(&Bs[s * SBS_H + row * LDH + seg], &Bg[(size_t)row * DIM + k0 + seg]);
        }
        cp_commit();
    };
    prefetch(0);
    prefetch(1);

    for (int kc = 0; kc < KCS; kc++) {
        if (kc + 2 < KCS)       { prefetch(kc + 2); cp_wait<2>(); }
        else if (kc + 2 == KCS) { cp_wait<1>(); }
        else                    { cp_wait<0>(); }
        __syncthreads();
        int s = kc % 3;
        const __half* Ab = &As[s * SA_H];
        const __half* Bb = &Bs[s * SBS_H];
        #pragma unroll
        for (int kk = 0; kk < 32; kk += 16) {
            wmma::load_matrix_sync(a0, &Ab[(wm * 32) * LDH + kk], LDH);
            wmma::load_matrix_sync(a1, &Ab[(wm * 32 + 16) * LDH + kk], LDH);
            #pragma unroll
            for (int ni = 0; ni < 4; ni++)
                wmma::load_matrix_sync(bf[ni], &Bb[(wn * 64 + ni * 16) * LDH + kk], LDH);
            #pragma unroll
            for (int ni = 0; ni < 4; ni++) {
                wmma::mma_sync(c[0][ni], a0, bf[ni], c[0][ni]);
                wmma::mma_sync(c[1][ni], a1, bf[ni], c[1][ni]);
            }
        }
        __syncthreads();
    }
    float* Sb = g_Sp[ks] + (size_t)b * JH * Nn;
    #pragma unroll
    for (int mi = 0; mi < 2; mi++)
        #pragma unroll
        for (int ni = 0; ni < 4; ni++)
            wmma::store_matrix_sync(&Sb[(size_t)(j0 + wm * 32 + mi * 16) * Nn + n0 + wn * 64 + ni * 16],
                                    c[mi][ni], Nn, wmma::mem_row_major);
}

// ============================================================================
// K3: masked softmax; sums 2 partials, writes half probs. grid 1536, 256 thr
// ============================================================================
__global__ void __launch_bounds__(256) k_softmax(const int* __restrict__ mask) {
    int bj = blockIdx.x;
    int b = bj / JH, j = bj % JH, r = j % Rr;
    const float* p0 = g_Sp[0] + (size_t)bj * Nn;
    const float* p1 = g_Sp[1] + (size_t)bj * Nn;
    __half* row = g_Sh + (size_t)bj * Nn;
    const int* mrow = mask + ((size_t)b * Rr + r) * MASKW;
    int tid = threadIdx.x, warp = tid >> 5, lane = tid & 31;
    __shared__ float red[8];

    float v[16];
    float mx = -3.0e38f;
    #pragma unroll
    for (int i = 0; i < 16; i++) {
        int n = tid + (i << 8);
        bool valid = (n < Rr) ? (n == r) : (mrow[n - Rr] != 0);
        v[i] = valid ? (p0[n] + p1[n]) : -3.0e38f;
        mx = fmaxf(mx, v[i]);
    }
    #pragma unroll
    for (int off = 16; off > 0; off >>= 1) mx = fmaxf(mx, __shfl_xor_sync(0xffffffffu, mx, off));
    if (lane == 0) red[warp] = mx;
    __syncthreads();
    if (warp == 0) {
        float t = (lane < 8) ? red[lane] : -3.0e38f;
        #pragma unroll
        for (int off = 4; off > 0; off >>= 1) t = fmaxf(t, __shfl_xor_sync(0xffffffffu, t, off));
        if (lane == 0) red[0] = t;
    }
    __syncthreads();
    mx = red[0];
    __syncthreads();

    float sum = 0.f;
    #pragma unroll
    for (int i = 0; i < 16; i++) { v[i] = __expf(v[i] - mx); sum += v[i]; }
    #pragma unroll
    for (int off = 16; off > 0; off >>= 1) sum += __shfl_xor_sync(0xffffffffu, sum, off);
    if (lane == 0) red[warp] = sum;
    __syncthreads();
    if (warp == 0) {
        float t = (lane < 8) ? red[lane] : 0.f;
        #pragma unroll
        for (int off = 4; off > 0; off >>= 1) t += __shfl_xor_sync(0xffffffffu, t, off);
        if (lane == 0) red[0] = t;
    }
    __syncthreads();
    float inv = 1.f / red[0];
    #pragma unroll
    for (int i = 0; i < 16; i++)
        row[tid + (i << 8)] = __float2half_rn(v[i] * inv);
}

// ============================================================================
// K4: partial Y = Ph[:, slab] @ xh[slab, :]  (fp16 wmma m16n16k16)
// CTA 64(j) x 256(c), k-chunk 32, 3-stage cp.async. warp 32x64.
// grid (6, 3, Bc*KSPY), 256 threads, dynamic smem
// ============================================================================
#define LDC2 264                          // half stride for B tile (256 + 8 pad)
#define SBY_H (32 * LDC2)                 // 8448 halves / stage
#define SMEM_Y ((3 * (SA_H + SBY_H)) * 2) // 66048 B
#define KCY (Nn / KSPY / 32)              // 32 chunks
__global__ void __launch_bounds__(256) k_gemmY(int dummy) {
    extern __shared__ __half sm[];
    __half* As = sm;
    __half* Bs = sm + 3 * SA_H;
    int b = blockIdx.z >> 2, ks = blockIdx.z & 3;
    int koff = ks * (Nn / KSPY);
    int j0 = blockIdx.y * 64, c0 = blockIdx.x * 256;
    const __half* Ag = g_Sh + ((size_t)b * JH + j0) * Nn + koff;
    const __half* Bg = g_xh + ((size_t)b * Nn + koff) * DIM;
    int tid = threadIdx.x;
    int warp = tid >> 5, wm = warp >> 2, wn = warp & 3;
    int arow = tid >> 2, aseg = (tid & 3) << 3;

    wmma::fragment<wmma::matrix_a, 16, 16, 16, __half, wmma::row_major> a0, a1;
    wmma::fragment<wmma::matrix_b, 16, 16, 16, __half, wmma::row_major> bf[4];
    wmma::fragment<wmma::accumulator, 16, 16, 16, float> c[2][4];
    #pragma unroll
    for (int mi = 0; mi < 2; mi++)
        #pragma unroll
        for (int ni = 0; ni < 4; ni++) wmma::fill_fragment(c[mi][ni], 0.f);

    auto prefetch = [&](int kc) {
        int s = kc % 3, k0 = kc << 5;
        cp16(&As[s * SA_H + arow * LDH + aseg], &Ag[(size_t)arow * Nn + k0 + aseg]);
        #pragma unroll
        for (int p = 0; p < 4; p++) {
            int i = tid + p * 256; int row = i >> 5, seg = (i & 31) << 3;
            cp16(&Bs[s * SBY_H + row * LDC2 + seg], &Bg[(size_t)(k0 + row) * DIM + c0 + seg]);
        }
        cp_commit();
    };
    prefetch(0);
    prefetch(1);

    for (int kc = 0; kc < KCY; kc++) {
        if (kc + 2 < KCY)       { prefetch(kc + 2); cp_wait<2>(); }
        else if (kc + 2 == KCY) { cp_wait<1>(); }
        else                    { cp_wait<0>(); }
        __syncthreads();
        int s = kc % 3;
        const __half* Ab = &As[s * SA_H];
        const __half* Bb = &Bs[s * SBY_H];
        #pragma unroll
        for (int kk = 0; kk < 32; kk += 16) {
            wmma::load_matrix_sync(a0, &Ab[(wm * 32) * LDH + kk], LDH);
            wmma::load_matrix_sync(a1, &Ab[(wm * 32 + 16) * LDH + kk], LDH);
            #pragma unroll
            for (int ni = 0; ni < 4; ni++)
                wmma::load_matrix_sync(bf[ni], &Bb[kk * LDC2 + wn * 64 + ni * 16], LDC2);
            #pragma unroll
            for (int ni = 0; ni < 4; ni++) {
                wmma::mma_sync(c[0][ni], a0, bf[ni], c[0][ni]);
                wmma::mma_sync(c[1][ni], a1, bf[ni], c[1][ni]);
            }
        }
        __syncthreads();
    }
    float* Yb = g_Yp[ks] + (size_t)b * JH * DIM;
    #pragma unroll
    for (int mi = 0; mi < 2; mi++)
        #pragma unroll
        for (int ni = 0; ni < 4; ni++)
            wmma::store_matrix_sync(&Yb[(size_t)(j0 + wm * 32 + mi * 16) * DIM + c0 + wn * 64 + ni * 16],
                                    c[mi][ni], DIM, wmma::mem_row_major);
}

// ============================================================================
// K5a: reduce 4 Y partials + x_cls[b][r][e] = sum_c Y[b][h*8+r][c] * Wv[e][c]
// ============================================================================
__global__ void __launch_bounds__(256) k_xcls(const float* __restrict__ Wv) {
    int b = blockIdx.x / Hh, h = blockIdx.x % Hh;
    __shared__ float Ys[Rr * DIM];
    size_t base = ((size_t)b * JH + h * Rr) * DIM;
    for (int i = threadIdx.x; i < Rr * DIM; i += 256)
        Ys[i] = g_Yp[0][base + i] + g_Yp[1][base + i] + g_Yp[2][base + i] + g_Yp[3][base + i];
    __syncthreads();
    int warp = threadIdx.x >> 5, lane = threadIdx.x & 31;
    #pragma unroll 1
    for (int i = 0; i < 8; i++) {
        int e = h * HD + warp * 8 + i;
        const float* wrow = Wv + (size_t)e * DIM;
        float acc[8] = {0.f,0.f,0.f,0.f,0.f,0.f,0.f,0.f};
        for (int c = lane; c < DIM; c += 32) {
            float w = wrow[c];
            #pragma unroll
            for (int r = 0; r < 8; r++) acc[r] += w * Ys[r * DIM + c];
        }
        #pragma unroll
        for (int r = 0; r < 8; r++)
            #pragma unroll
            for (int off = 16; off > 0; off >>= 1)
                acc[r] += __shfl_xor_sync(0xffffffffu, acc[r], off);
        if (lane < 8)
            g_xcls[((size_t)b * Rr + lane) * DIM + e] = acc[lane];
    }
}

// ============================================================================
// K5b: out[b][r][o] = dot(x_cls[b][r][:], Wp[o][:]) + bp[o]
// ============================================================================
__global__ void __launch_bounds__(256) k_out(const float* __restrict__ Wp,
                                             const float* __restrict__ bp,
                                             float* __restrict__ out) {
    int b = blockIdx.x / Hh, oblk = blockIdx.x % Hh;
    __shared__ float xcs[Rr * DIM];
    for (int i = threadIdx.x; i < Rr * DIM; i += 256)
        xcs[i] = g_xcls[(size_t)b * Rr * DIM + i];
    __syncthreads();
    int warp = threadIdx.x >> 5, lane = threadIdx.x & 31;
    #pragma unroll 1
    for (int i = 0; i < 8; i++) {
        int o = oblk * HD + warp * 8 + i;
        const float* wrow = Wp + (size_t)o * DIM;
        float acc[8] = {0.f,0.f,0.f,0.f,0.f,0.f,0.f,0.f};
        for (int c = lane; c < DIM; c += 32) {
            float w = wrow[c];
            #pragma unroll
            for (int r = 0; r < 8; r++) acc[r] += w * xcs[r * DIM + c];
        }
        #pragma unroll
        for (int r = 0; r < 8; r++)
            #pragma unroll
            for (int off = 16; off > 0; off >>= 1)
                acc[r] += __shfl_xor_sync(0xffffffffu, acc[r], off);
        if (lane < 8)
            out[((size_t)b * Rr + lane) * DIM + o] = acc[lane] + bp[o];
    }
}

// ============================================================================
extern "C" void kernel_launch(void* const* d_in, const int* in_sizes, int n_in,
                              void* d_out, int out_size) {
    const float* x    = (const float*)d_in[0];
    const int*   mask = (const int*)d_in[1];
    const float* Wq   = (const float*)d_in[2];
    const float* Wk   = (const float*)d_in[3];
    const float* Wv   = (const float*)d_in[4];
    const float* Wp   = (const float*)d_in[5];
    const float* bp   = (const float*)d_in[6];
    float*       out  = (float*)d_out;

    cudaFuncSetAttribute(k_gemmS, cudaFuncAttributeMaxDynamicSharedMemorySize, SMEM_S);
    cudaFuncSetAttribute(k_gemmY, cudaFuncAttributeMaxDynamicSharedMemorySize, SMEM_Y);

    k_xh     <<<(int)(((size_t)Bc * Nn * DIM) / (256 * 8)), 256>>>(x);
    k_qg     <<<Bc * Hh, 256>>>(x, Wq, Wk);
    k_gemmS  <<<dim3(Nn / 256, JH / 64, Bc * KSPS), 256, SMEM_S>>>(0);
    k_softmax<<<Bc * JH, 256>>>(mask);
    k_gemmY  <<<dim3(DIM / 256, JH / 64, Bc * KSPY), 256, SMEM_Y>>>(0);
    k_xcls   <<<Bc * Hh, 256>>>(Wv);
    k_out    <<<Bc * Hh, 256>>>(Wp, bp, out);
}